// round 1
// baseline (speedup 1.0000x reference)
#include <cuda_runtime.h>
#include <math.h>

#define NPTS 65536
#define CDIM 256
#define HEADS 16
#define HD 16
#define KWIN 32
#define NWIN 2048
#define LXYZ 40
#define LRGB 32
#define QSF 4.0f
#define CQSF 8.0f
#define QK_SCALE 0.25f

// Scratch (allocation-free rule: device globals)
__device__ float g_qkv[(size_t)NPTS * 768];
__device__ float g_mid[(size_t)NPTS * CDIM];

// ---------------------------------------------------------------------------
// SGEMM: C[M,N] = A[M,K] @ W[N,K]^T + bias[N]
// 128x128 tile, BK=8, 256 threads, 8x8 per thread. M,N multiples of 128, K of 8.
// ---------------------------------------------------------------------------
__global__ __launch_bounds__(256, 2) void sgemm_nt(
    const float* __restrict__ A, const float* __restrict__ Wm,
    const float* __restrict__ bias, float* __restrict__ Cm,
    int M, int N, int Kd)
{
    __shared__ float As[8][128];
    __shared__ float Bs[8][128];
    const int tid = threadIdx.x;
    const int tx = tid & 15;
    const int ty = tid >> 4;
    const int brow = blockIdx.y * 128;
    const int bcol = blockIdx.x * 128;
    const int lrow = tid >> 1;
    const int lcol = (tid & 1) * 4;

    const float* Ap = A + (size_t)(brow + lrow) * Kd + lcol;
    const float* Wp = Wm + (size_t)(bcol + lrow) * Kd + lcol;

    float acc[8][8];
#pragma unroll
    for (int m = 0; m < 8; m++)
#pragma unroll
        for (int n = 0; n < 8; n++) acc[m][n] = 0.f;

    for (int kt = 0; kt < Kd; kt += 8) {
        float4 av = *(const float4*)(Ap + kt);
        float4 wv = *(const float4*)(Wp + kt);
        __syncthreads();
        As[lcol + 0][lrow] = av.x; As[lcol + 1][lrow] = av.y;
        As[lcol + 2][lrow] = av.z; As[lcol + 3][lrow] = av.w;
        Bs[lcol + 0][lrow] = wv.x; Bs[lcol + 1][lrow] = wv.y;
        Bs[lcol + 2][lrow] = wv.z; Bs[lcol + 3][lrow] = wv.w;
        __syncthreads();
#pragma unroll
        for (int k = 0; k < 8; k++) {
            float a[8], b[8];
#pragma unroll
            for (int m = 0; m < 8; m++) a[m] = As[k][ty * 8 + m];
#pragma unroll
            for (int n = 0; n < 8; n++) b[n] = Bs[k][tx * 8 + n];
#pragma unroll
            for (int m = 0; m < 8; m++)
#pragma unroll
                for (int n = 0; n < 8; n++) acc[m][n] += a[m] * b[n];
        }
    }

#pragma unroll
    for (int m = 0; m < 8; m++) {
        int row = brow + ty * 8 + m;
#pragma unroll
        for (int n = 0; n < 8; n += 4) {
            int col = bcol + tx * 8 + n;
            float4 o;
            o.x = acc[m][n + 0] + bias[col + 0];
            o.y = acc[m][n + 1] + bias[col + 1];
            o.z = acc[m][n + 2] + bias[col + 2];
            o.w = acc[m][n + 3] + bias[col + 3];
            *(float4*)&Cm[(size_t)row * N + col] = o;
        }
    }
}

// ---------------------------------------------------------------------------
// Windowed attention with relative position tables
// ---------------------------------------------------------------------------
__device__ __forceinline__ float dot16(const float4 a0, const float4 a1,
                                       const float4 a2, const float4 a3,
                                       const float4* __restrict__ b)
{
    float4 b0 = b[0], b1 = b[1], b2 = b[2], b3 = b[3];
    float s;
    s  = a0.x * b0.x; s += a0.y * b0.y; s += a0.z * b0.z; s += a0.w * b0.w;
    s += a1.x * b1.x; s += a1.y * b1.y; s += a1.z * b1.z; s += a1.w * b1.w;
    s += a2.x * b2.x; s += a2.y * b2.y; s += a2.z * b2.z; s += a2.w * b2.w;
    s += a3.x * b3.x; s += a3.y * b3.y; s += a3.z * b3.z; s += a3.w * b3.w;
    return s;
}

// dynamic smem layout (floats):
//   sk    [32*256]  @ 0
//   sv    [32*256]  @ 8192
//   satt  [32*256]  @ 16384   (satt[j*256 + tid])
//   scoord[192]     @ 24576
//   spt   [32] int  @ 24768
//   sidx  [6144] u8 @ 24800 (byte offset 99200)
#define ATTN_SMEM_BYTES (24800 * 4 + 6144)

__global__ __launch_bounds__(256, 2) void win_attn(
    const float* __restrict__ n_coords, const int* __restrict__ n2n,
    const float* __restrict__ ktab_xyz, const float* __restrict__ qtab_xyz,
    const float* __restrict__ vtab_xyz,
    const float* __restrict__ ktab_rgb, const float* __restrict__ qtab_rgb,
    const float* __restrict__ vtab_rgb)
{
    extern __shared__ float smem[];
    float* sk = smem;
    float* sv = smem + 8192;
    float* satt = smem + 16384;
    float* scoord = smem + 24576;
    int* spt = (int*)(smem + 24768);
    unsigned char* sidx = (unsigned char*)(smem + 24800);

    const int tid = threadIdx.x;
    const int w = blockIdx.x;

    if (tid < KWIN) spt[tid] = n2n[w * KWIN + tid];
    __syncthreads();

    if (tid < 192) {
        int i = tid / 6, d = tid % 6;
        float s = (d < 3) ? QSF : CQSF;
        scoord[tid] = n_coords[(size_t)spt[i] * 6 + d] * s;
    }
    // stage K and V rows into smem (coalesced)
    for (int i = 0; i < KWIN; ++i) {
        size_t base = (size_t)spt[i] * 768;
        sk[i * 256 + tid] = g_qkv[base + 256 + tid];
        sv[i * 256 + tid] = g_qkv[base + 512 + tid];
    }
    __syncthreads();

    // precompute relative table indices per (i,j) pair, packed uint8
#pragma unroll
    for (int r = 0; r < 4; ++r) {
        int p = r * 256 + tid;
        int i = p >> 5, j = p & 31;
        const float* ci = scoord + i * 6;
        const float* cj = scoord + j * 6;
        unsigned char* ip = sidx + p * 6;
#pragma unroll
        for (int d = 0; d < 3; d++) {
            int l = (int)floorf(ci[d] - cj[d]) + LXYZ / 2;
            l = min(max(l, 0), LXYZ - 1);
            ip[d] = (unsigned char)l;
        }
#pragma unroll
        for (int d = 0; d < 3; d++) {
            int l = (int)floorf(ci[3 + d] - cj[3 + d]) + LRGB / 2;
            l = min(max(l, 0), LRGB - 1);
            ip[3 + d] = (unsigned char)l;
        }
    }
    __syncthreads();

    // each thread owns rows (i,h); 512 rows total, 2 per thread
    for (int r = 0; r < 2; ++r) {
        const int row = r * 256 + tid;
        const int i = row >> 4;
        const int h = row & 15;
        const int pt = spt[i];

        // q row (scaled) in registers
        const float4* qp = (const float4*)(g_qkv + (size_t)pt * 768 + h * 16);
        float4 q0 = qp[0], q1 = qp[1], q2 = qp[2], q3 = qp[3];
        q0.x *= QK_SCALE; q0.y *= QK_SCALE; q0.z *= QK_SCALE; q0.w *= QK_SCALE;
        q1.x *= QK_SCALE; q1.y *= QK_SCALE; q1.z *= QK_SCALE; q1.w *= QK_SCALE;
        q2.x *= QK_SCALE; q2.y *= QK_SCALE; q2.z *= QK_SCALE; q2.w *= QK_SCALE;
        q3.x *= QK_SCALE; q3.y *= QK_SCALE; q3.z *= QK_SCALE; q3.w *= QK_SCALE;

        // logits
        for (int j = 0; j < KWIN; ++j) {
            const float4* kj = (const float4*)(sk + j * 256 + h * 16);
            float4 k0 = kj[0], k1 = kj[1], k2 = kj[2], k3 = kj[3];
            float acc;
            acc  = q0.x * k0.x + q0.y * k0.y + q0.z * k0.z + q0.w * k0.w;
            acc += q1.x * k1.x + q1.y * k1.y + q1.z * k1.z + q1.w * k1.w;
            acc += q2.x * k2.x + q2.y * k2.y + q2.z * k2.z + q2.w * k2.w;
            acc += q3.x * k3.x + q3.y * k3.y + q3.z * k3.z + q3.w * k3.w;

            const unsigned char* ip = sidx + (i * 32 + j) * 6;
#pragma unroll
            for (int d = 0; d < 3; d++) {
                int off = ((d * LXYZ + ip[d]) * 16 + h) * 16;
                acc += dot16(q0, q1, q2, q3, (const float4*)(ktab_xyz + off));
                acc += dot16(k0, k1, k2, k3, (const float4*)(qtab_xyz + off));
            }
#pragma unroll
            for (int d = 0; d < 3; d++) {
                int off = ((d * LRGB + ip[3 + d]) * 16 + h) * 16;
                acc += dot16(q0, q1, q2, q3, (const float4*)(ktab_rgb + off));
                acc += dot16(k0, k1, k2, k3, (const float4*)(qtab_rgb + off));
            }
            satt[j * 256 + tid] = acc;
        }

        // softmax over j
        float mmax = -1e30f;
        for (int j = 0; j < KWIN; ++j) mmax = fmaxf(mmax, satt[j * 256 + tid]);
        float ssum = 0.f;
        for (int j = 0; j < KWIN; ++j) {
            float e = __expf(satt[j * 256 + tid] - mmax);
            satt[j * 256 + tid] = e;
            ssum += e;
        }
        const float inv = 1.0f / ssum;

        // output: out[i,h,:] = sum_j a * (v[j,h,:] + 6 gathered value-table rows)
        float4 o0 = {0, 0, 0, 0}, o1 = {0, 0, 0, 0}, o2 = {0, 0, 0, 0}, o3 = {0, 0, 0, 0};
        for (int j = 0; j < KWIN; ++j) {
            float a = satt[j * 256 + tid] * inv;
            const float4* vj = (const float4*)(sv + j * 256 + h * 16);
            const unsigned char* ip = sidx + (i * 32 + j) * 6;
            const float4* t0 = (const float4*)(vtab_xyz + ((0 * LXYZ + ip[0]) * 16 + h) * 16);
            const float4* t1 = (const float4*)(vtab_xyz + ((1 * LXYZ + ip[1]) * 16 + h) * 16);
            const float4* t2 = (const float4*)(vtab_xyz + ((2 * LXYZ + ip[2]) * 16 + h) * 16);
            const float4* t3 = (const float4*)(vtab_rgb + ((0 * LRGB + ip[3]) * 16 + h) * 16);
            const float4* t4 = (const float4*)(vtab_rgb + ((1 * LRGB + ip[4]) * 16 + h) * 16);
            const float4* t5 = (const float4*)(vtab_rgb + ((2 * LRGB + ip[5]) * 16 + h) * 16);
#pragma unroll
            for (int s = 0; s < 4; ++s) {
                float4 vv = vj[s];
                float4 a0 = t0[s], a1 = t1[s], a2 = t2[s], a3 = t3[s], a4 = t4[s], a5 = t5[s];
                float sx = vv.x + a0.x + a1.x + a2.x + a3.x + a4.x + a5.x;
                float sy = vv.y + a0.y + a1.y + a2.y + a3.y + a4.y + a5.y;
                float sz = vv.z + a0.z + a1.z + a2.z + a3.z + a4.z + a5.z;
                float sw = vv.w + a0.w + a1.w + a2.w + a3.w + a4.w + a5.w;
                float4* o = (s == 0) ? &o0 : (s == 1) ? &o1 : (s == 2) ? &o2 : &o3;
                o->x += a * sx; o->y += a * sy; o->z += a * sz; o->w += a * sw;
            }
        }

        float4* op = (float4*)(g_mid + (size_t)pt * CDIM + h * 16);
        op[0] = o0; op[1] = o1; op[2] = o2; op[3] = o3;
    }
}

// ---------------------------------------------------------------------------
extern "C" void kernel_launch(void* const* d_in, const int* in_sizes, int n_in,
                              void* d_out, int out_size)
{
    const float* feats    = (const float*)d_in[0];
    const float* n_coords = (const float*)d_in[1];
    const int*   n2n      = (const int*)d_in[2];
    const float* q_xyz    = (const float*)d_in[3];
    const float* k_xyz    = (const float*)d_in[4];
    const float* v_xyz    = (const float*)d_in[5];
    const float* q_rgb    = (const float*)d_in[6];
    const float* k_rgb    = (const float*)d_in[7];
    const float* v_rgb    = (const float*)d_in[8];
    const float* qkv_w    = (const float*)d_in[9];
    const float* qkv_b    = (const float*)d_in[10];
    const float* proj_w   = (const float*)d_in[11];
    const float* proj_b   = (const float*)d_in[12];
    float* out = (float*)d_out;

    float *qkv_p = nullptr, *mid_p = nullptr;
    cudaGetSymbolAddress((void**)&qkv_p, g_qkv);
    cudaGetSymbolAddress((void**)&mid_p, g_mid);

    cudaFuncSetAttribute(win_attn, cudaFuncAttributeMaxDynamicSharedMemorySize,
                         ATTN_SMEM_BYTES);

    // 1) QKV projection: [65536,256] x [768,256]^T
    dim3 g1(768 / 128, NPTS / 128);
    sgemm_nt<<<g1, 256>>>(feats, qkv_w, qkv_b, qkv_p, NPTS, 768, CDIM);

    // 2) windowed attention (reads g_qkv, writes g_mid scattered to orig order)
    win_attn<<<NWIN, 256, ATTN_SMEM_BYTES>>>(n_coords, n2n,
                                             k_xyz, q_xyz, v_xyz,
                                             k_rgb, q_rgb, v_rgb);

    // 3) output projection: [65536,256] x [256,256]^T
    dim3 g2(CDIM / 128, NPTS / 128);
    sgemm_nt<<<g2, 256>>>(mid_p, proj_w, proj_b, out, NPTS, CDIM, CDIM);
}

// round 2
// speedup vs baseline: 1.2181x; 1.2181x over previous
#include <cuda_runtime.h>
#include <math.h>

#define NPTS 65536
#define CDIM 256
#define HEADS 16
#define HD 16
#define KWIN 32
#define NWIN 2048
#define LXYZ 40
#define LRGB 32
#define QSF 4.0f
#define CQSF 8.0f
#define QK_SCALE 0.25f

// Scratch (allocation-free rule: device globals)
__device__ float g_qkv[(size_t)NPTS * 768];
__device__ float g_mid[(size_t)NPTS * CDIM];

// ---------------------------------------------------------------------------
// SGEMM: C[M,N] = A[M,K] @ W[N,K]^T + bias[N]
// 128x128 tile, BK=8, 256 threads, 8x8 per thread, double-buffered smem.
// ---------------------------------------------------------------------------
__global__ __launch_bounds__(256, 2) void sgemm_nt(
    const float* __restrict__ A, const float* __restrict__ Wm,
    const float* __restrict__ bias, float* __restrict__ Cm,
    int M, int N, int Kd)
{
    __shared__ float As[2][8][128];
    __shared__ float Bs[2][8][128];
    const int tid = threadIdx.x;
    const int tx = tid & 15;
    const int ty = tid >> 4;
    const int brow = blockIdx.y * 128;
    const int bcol = blockIdx.x * 128;
    const int lrow = tid >> 1;
    const int lcol = (tid & 1) * 4;

    const float* Ap = A + (size_t)(brow + lrow) * Kd + lcol;
    const float* Wp = Wm + (size_t)(bcol + lrow) * Kd + lcol;

    float acc[8][8];
#pragma unroll
    for (int m = 0; m < 8; m++)
#pragma unroll
        for (int n = 0; n < 8; n++) acc[m][n] = 0.f;

    // prologue: load tile 0 into buffer 0
    {
        float4 av = *(const float4*)Ap;
        float4 wv = *(const float4*)Wp;
        As[0][lcol + 0][lrow] = av.x; As[0][lcol + 1][lrow] = av.y;
        As[0][lcol + 2][lrow] = av.z; As[0][lcol + 3][lrow] = av.w;
        Bs[0][lcol + 0][lrow] = wv.x; Bs[0][lcol + 1][lrow] = wv.y;
        Bs[0][lcol + 2][lrow] = wv.z; Bs[0][lcol + 3][lrow] = wv.w;
    }
    __syncthreads();

    const int nT = Kd / 8;
    for (int n = 0; n < nT; n++) {
        const int b = n & 1;
        float4 av2, wv2;
        const bool more = (n + 1 < nT);
        if (more) {
            av2 = *(const float4*)(Ap + (n + 1) * 8);
            wv2 = *(const float4*)(Wp + (n + 1) * 8);
        }
#pragma unroll
        for (int k = 0; k < 8; k++) {
            float a[8], bb[8];
#pragma unroll
            for (int m = 0; m < 8; m++) a[m] = As[b][k][ty * 8 + m];
#pragma unroll
            for (int c = 0; c < 8; c++) bb[c] = Bs[b][k][tx * 8 + c];
#pragma unroll
            for (int m = 0; m < 8; m++)
#pragma unroll
                for (int c = 0; c < 8; c++) acc[m][c] += a[m] * bb[c];
        }
        if (more) {
            const int b2 = b ^ 1;
            As[b2][lcol + 0][lrow] = av2.x; As[b2][lcol + 1][lrow] = av2.y;
            As[b2][lcol + 2][lrow] = av2.z; As[b2][lcol + 3][lrow] = av2.w;
            Bs[b2][lcol + 0][lrow] = wv2.x; Bs[b2][lcol + 1][lrow] = wv2.y;
            Bs[b2][lcol + 2][lrow] = wv2.z; Bs[b2][lcol + 3][lrow] = wv2.w;
        }
        __syncthreads();
    }

#pragma unroll
    for (int m = 0; m < 8; m++) {
        int row = brow + ty * 8 + m;
#pragma unroll
        for (int c = 0; c < 8; c += 4) {
            int col = bcol + tx * 8 + c;
            float4 o;
            o.x = acc[m][c + 0] + bias[col + 0];
            o.y = acc[m][c + 1] + bias[col + 1];
            o.z = acc[m][c + 2] + bias[col + 2];
            o.w = acc[m][c + 3] + bias[col + 3];
            *(float4*)&Cm[(size_t)row * N + col] = o;
        }
    }
}

// ---------------------------------------------------------------------------
// Windowed attention with relative position tables
// ---------------------------------------------------------------------------
__device__ __forceinline__ float4 ld4(const float* __restrict__ p) {
    return *(const float4*)p;
}
__device__ __forceinline__ float4 add4(float4 a, float4 b) {
    return make_float4(a.x + b.x, a.y + b.y, a.z + b.z, a.w + b.w);
}
__device__ __forceinline__ float dot4(float4 a, float4 b) {
    return a.x * b.x + a.y * b.y + a.z * b.z + a.w * b.w;
}

// dynamic smem layout (float offsets):
//   sk     [32*320]  @ 0       (padded: h-stride 20 floats -> conflict-free)
//   satt   [32*256]  @ 10240
//   scoord [192]     @ 18432
//   spt    [32] int  @ 18624
//   sidx2  [1024] u2 @ 18656   (uint2-packed 6 indices per (i,j))
#define ATTN_SMEM_FLOATS 20704
#define ATTN_SMEM_BYTES (ATTN_SMEM_FLOATS * 4)

__global__ __launch_bounds__(256, 2) void win_attn(
    const float* __restrict__ n_coords, const int* __restrict__ n2n,
    const float* __restrict__ ktab_xyz, const float* __restrict__ qtab_xyz,
    const float* __restrict__ vtab_xyz,
    const float* __restrict__ ktab_rgb, const float* __restrict__ qtab_rgb,
    const float* __restrict__ vtab_rgb)
{
    extern __shared__ float smem[];
    float* sk = smem;
    float* satt = smem + 10240;
    float* scoord = smem + 18432;
    int* spt = (int*)(smem + 18624);
    uint2* sidx2 = (uint2*)(smem + 18656);

    const int tid = threadIdx.x;
    const int w = blockIdx.x;

    if (tid < KWIN) spt[tid] = n2n[w * KWIN + tid];
    __syncthreads();

    if (tid < 192) {
        int i = tid / 6, d = tid % 6;
        float s = (d < 3) ? QSF : CQSF;
        scoord[tid] = n_coords[(size_t)spt[i] * 6 + d] * s;
    }
    // stage K rows into padded smem (coalesced global reads)
    {
        const int h = tid >> 4, c = tid & 15;
        for (int j = 0; j < KWIN; ++j) {
            sk[j * 320 + h * 20 + c] = g_qkv[(size_t)spt[j] * 768 + 256 + tid];
        }
    }
    __syncthreads();

    // precompute packed relative indices per (i,j) pair
#pragma unroll
    for (int r = 0; r < 4; ++r) {
        int p = r * 256 + tid;
        int i = p >> 5, j = p & 31;
        const float* ci = scoord + i * 6;
        const float* cj = scoord + j * 6;
        int l[6];
#pragma unroll
        for (int d = 0; d < 3; d++) {
            int v = (int)floorf(ci[d] - cj[d]) + LXYZ / 2;
            l[d] = min(max(v, 0), LXYZ - 1);
        }
#pragma unroll
        for (int d = 0; d < 3; d++) {
            int v = (int)floorf(ci[3 + d] - cj[3 + d]) + LRGB / 2;
            l[3 + d] = min(max(v, 0), LRGB - 1);
        }
        unsigned lo = (unsigned)l[0] | ((unsigned)l[1] << 8) |
                      ((unsigned)l[2] << 16) | ((unsigned)l[3] << 24);
        unsigned hi = (unsigned)l[4] | ((unsigned)l[5] << 8);
        sidx2[p] = make_uint2(lo, hi);
    }
    __syncthreads();

    // each thread owns rows (i,h); 512 rows total, 2 per thread
    for (int r = 0; r < 2; ++r) {
        const int row = r * 256 + tid;
        const int i = row >> 4;
        const int h = row & 15;
        const int pt = spt[i];

        const float* ktx = ktab_xyz + h * 16;
        const float* qtx = qtab_xyz + h * 16;
        const float* vtx = vtab_xyz + h * 16;
        const float* ktr = ktab_rgb + h * 16;
        const float* qtr = qtab_rgb + h * 16;
        const float* vtr = vtab_rgb + h * 16;

        // q row (scaled) in registers
        float4 q[4];
        {
            const float4* qp = (const float4*)(g_qkv + (size_t)pt * 768 + h * 16);
#pragma unroll
            for (int t = 0; t < 4; t++) {
                float4 v = qp[t];
                q[t] = make_float4(v.x * QK_SCALE, v.y * QK_SCALE,
                                   v.z * QK_SCALE, v.w * QK_SCALE);
            }
        }

        // ---- logits ----
#pragma unroll 2
        for (int j = 0; j < KWIN; ++j) {
            const uint2 pk = sidx2[i * 32 + j];
            const int r0 = (int)(pk.x & 255) << 8;
            const int r1 = (int)(40 + ((pk.x >> 8) & 255)) << 8;
            const int r2 = (int)(80 + ((pk.x >> 16) & 255)) << 8;
            const int r3 = (int)(pk.x >> 24) << 8;
            const int r4 = (int)(32 + (pk.y & 255)) << 8;
            const int r5 = (int)(64 + ((pk.y >> 8) & 255)) << 8;

            const float4* kj = (const float4*)(sk + j * 320 + h * 20);
            float acc = 0.f;
#pragma unroll
            for (int t = 0; t < 4; t++) {
                float4 kt = kj[t];
                // q-side: sum of 6 key-table rows, one dot with q
                float4 qs = add4(add4(add4(ld4(ktx + r0 + 4 * t), ld4(ktx + r1 + 4 * t)),
                                      add4(ld4(ktx + r2 + 4 * t), ld4(ktr + r3 + 4 * t))),
                                 add4(ld4(ktr + r4 + 4 * t), ld4(ktr + r5 + 4 * t)));
                // k-side: sum of 6 query-table rows, one dot with k
                float4 ks = add4(add4(add4(ld4(qtx + r0 + 4 * t), ld4(qtx + r1 + 4 * t)),
                                      add4(ld4(qtx + r2 + 4 * t), ld4(qtr + r3 + 4 * t))),
                                 add4(ld4(qtr + r4 + 4 * t), ld4(qtr + r5 + 4 * t)));
                acc += dot4(q[t], add4(kt, qs)) + dot4(kt, ks);
            }
            satt[j * 256 + tid] = acc;
        }

        // ---- softmax over j ----
        float mmax = -1e30f;
        for (int j = 0; j < KWIN; ++j) mmax = fmaxf(mmax, satt[j * 256 + tid]);
        float ssum = 0.f;
        for (int j = 0; j < KWIN; ++j) {
            float e = __expf(satt[j * 256 + tid] - mmax);
            satt[j * 256 + tid] = e;
            ssum += e;
        }
        const float inv = 1.0f / ssum;

        // ---- output: out[i,h,:] = sum_j a * (v[j,h,:] + 6 value-table rows) ----
        float4 o[4] = {{0,0,0,0},{0,0,0,0},{0,0,0,0},{0,0,0,0}};
#pragma unroll 2
        for (int j = 0; j < KWIN; ++j) {
            const float a = satt[j * 256 + tid] * inv;
            const uint2 pk = sidx2[i * 32 + j];
            const int r0 = (int)(pk.x & 255) << 8;
            const int r1 = (int)(40 + ((pk.x >> 8) & 255)) << 8;
            const int r2 = (int)(80 + ((pk.x >> 16) & 255)) << 8;
            const int r3 = (int)(pk.x >> 24) << 8;
            const int r4 = (int)(32 + (pk.y & 255)) << 8;
            const int r5 = (int)(64 + ((pk.y >> 8) & 255)) << 8;
            const float* vp = g_qkv + (size_t)spt[j] * 768 + 512 + h * 16;
#pragma unroll
            for (int t = 0; t < 4; t++) {
                float4 s = add4(add4(add4(ld4(vtx + r0 + 4 * t), ld4(vtx + r1 + 4 * t)),
                                     add4(ld4(vtx + r2 + 4 * t), ld4(vtr + r3 + 4 * t))),
                                add4(add4(ld4(vtr + r4 + 4 * t), ld4(vtr + r5 + 4 * t)),
                                     ld4(vp + 4 * t)));
                o[t].x += a * s.x; o[t].y += a * s.y;
                o[t].z += a * s.z; o[t].w += a * s.w;
            }
        }

        float4* op = (float4*)(g_mid + (size_t)pt * CDIM + h * 16);
#pragma unroll
        for (int t = 0; t < 4; t++) op[t] = o[t];
    }
}

// ---------------------------------------------------------------------------
extern "C" void kernel_launch(void* const* d_in, const int* in_sizes, int n_in,
                              void* d_out, int out_size)
{
    const float* feats    = (const float*)d_in[0];
    const float* n_coords = (const float*)d_in[1];
    const int*   n2n      = (const int*)d_in[2];
    const float* q_xyz    = (const float*)d_in[3];
    const float* k_xyz    = (const float*)d_in[4];
    const float* v_xyz    = (const float*)d_in[5];
    const float* q_rgb    = (const float*)d_in[6];
    const float* k_rgb    = (const float*)d_in[7];
    const float* v_rgb    = (const float*)d_in[8];
    const float* qkv_w    = (const float*)d_in[9];
    const float* qkv_b    = (const float*)d_in[10];
    const float* proj_w   = (const float*)d_in[11];
    const float* proj_b   = (const float*)d_in[12];
    float* out = (float*)d_out;

    float *qkv_p = nullptr, *mid_p = nullptr;
    cudaGetSymbolAddress((void**)&qkv_p, g_qkv);
    cudaGetSymbolAddress((void**)&mid_p, g_mid);

    cudaFuncSetAttribute(win_attn, cudaFuncAttributeMaxDynamicSharedMemorySize,
                         ATTN_SMEM_BYTES);

    // 1) QKV projection: [65536,256] x [768,256]^T
    dim3 g1(768 / 128, NPTS / 128);
    sgemm_nt<<<g1, 256>>>(feats, qkv_w, qkv_b, qkv_p, NPTS, 768, CDIM);

    // 2) windowed attention (reads g_qkv, writes g_mid scattered to orig order)
    win_attn<<<NWIN, 256, ATTN_SMEM_BYTES>>>(n_coords, n2n,
                                             k_xyz, q_xyz, v_xyz,
                                             k_rgb, q_rgb, v_rgb);

    // 3) output projection: [65536,256] x [256,256]^T
    dim3 g2(CDIM / 128, NPTS / 128);
    sgemm_nt<<<g2, 256>>>(mid_p, proj_w, proj_b, out, NPTS, CDIM, CDIM);
}

// round 4
// speedup vs baseline: 2.7671x; 2.2716x over previous
#include <cuda_runtime.h>
#include <cuda_fp16.h>
#include <math.h>

#define NPTS 65536
#define CDIM 256
#define HEADS 16
#define HD 16
#define KWIN 32
#define NWIN 2048
#define LXYZ 40
#define LRGB 32
#define QSF 4.0f
#define CQSF 8.0f
#define QK_SCALE 0.25f

// half-table layout offsets (in halfs)
#define T_KX 0
#define T_QX 30720
#define T_VX 61440
#define T_KR 92160
#define T_QR 116736
#define T_VR 141312
#define T_TOT 165888

// Scratch (allocation-free rule: device globals)
__device__ float g_qkv[(size_t)NPTS * 768];
__device__ float g_mid[(size_t)NPTS * CDIM];
__device__ __align__(16) __half g_tabh[T_TOT];

// ---------------------------------------------------------------------------
// Convert the 6 fp32 relative-position tables to fp16
// ---------------------------------------------------------------------------
__global__ void cvt_tabs(const float* __restrict__ kx, const float* __restrict__ qx,
                         const float* __restrict__ vx, const float* __restrict__ kr,
                         const float* __restrict__ qr, const float* __restrict__ vr)
{
    int i = blockIdx.x * 256 + threadIdx.x;
    if (i < 30720) {
        g_tabh[T_KX + i] = __float2half(kx[i]);
        g_tabh[T_QX + i] = __float2half(qx[i]);
        g_tabh[T_VX + i] = __float2half(vx[i]);
    }
    if (i < 24576) {
        g_tabh[T_KR + i] = __float2half(kr[i]);
        g_tabh[T_QR + i] = __float2half(qr[i]);
        g_tabh[T_VR + i] = __float2half(vr[i]);
    }
}

// ---------------------------------------------------------------------------
// SGEMM: C[M,N] = A[M,K] @ W[N,K]^T + bias[N]
// 128x128 tile, BK=8, 256 threads, 8x8 per thread, double-buffered smem.
// ---------------------------------------------------------------------------
__global__ __launch_bounds__(256, 2) void sgemm_nt(
    const float* __restrict__ A, const float* __restrict__ Wm,
    const float* __restrict__ bias, float* __restrict__ Cm,
    int M, int N, int Kd)
{
    __shared__ float As[2][8][128];
    __shared__ float Bs[2][8][128];
    const int tid = threadIdx.x;
    const int tx = tid & 15;
    const int ty = tid >> 4;
    const int brow = blockIdx.y * 128;
    const int bcol = blockIdx.x * 128;
    const int lrow = tid >> 1;
    const int lcol = (tid & 1) * 4;

    const float* Ap = A + (size_t)(brow + lrow) * Kd + lcol;
    const float* Wp = Wm + (size_t)(bcol + lrow) * Kd + lcol;

    float acc[8][8];
#pragma unroll
    for (int m = 0; m < 8; m++)
#pragma unroll
        for (int n = 0; n < 8; n++) acc[m][n] = 0.f;

    {
        float4 av = *(const float4*)Ap;
        float4 wv = *(const float4*)Wp;
        As[0][lcol + 0][lrow] = av.x; As[0][lcol + 1][lrow] = av.y;
        As[0][lcol + 2][lrow] = av.z; As[0][lcol + 3][lrow] = av.w;
        Bs[0][lcol + 0][lrow] = wv.x; Bs[0][lcol + 1][lrow] = wv.y;
        Bs[0][lcol + 2][lrow] = wv.z; Bs[0][lcol + 3][lrow] = wv.w;
    }
    __syncthreads();

    const int nT = Kd / 8;
    for (int n = 0; n < nT; n++) {
        const int b = n & 1;
        float4 av2, wv2;
        const bool more = (n + 1 < nT);
        if (more) {
            av2 = *(const float4*)(Ap + (n + 1) * 8);
            wv2 = *(const float4*)(Wp + (n + 1) * 8);
        }
#pragma unroll
        for (int k = 0; k < 8; k++) {
            float a[8], bb[8];
#pragma unroll
            for (int m = 0; m < 8; m++) a[m] = As[b][k][ty * 8 + m];
#pragma unroll
            for (int c = 0; c < 8; c++) bb[c] = Bs[b][k][tx * 8 + c];
#pragma unroll
            for (int m = 0; m < 8; m++)
#pragma unroll
                for (int c = 0; c < 8; c++) acc[m][c] += a[m] * bb[c];
        }
        if (more) {
            const int b2 = b ^ 1;
            As[b2][lcol + 0][lrow] = av2.x; As[b2][lcol + 1][lrow] = av2.y;
            As[b2][lcol + 2][lrow] = av2.z; As[b2][lcol + 3][lrow] = av2.w;
            Bs[b2][lcol + 0][lrow] = wv2.x; Bs[b2][lcol + 1][lrow] = wv2.y;
            Bs[b2][lcol + 2][lrow] = wv2.z; Bs[b2][lcol + 3][lrow] = wv2.w;
        }
        __syncthreads();
    }

#pragma unroll
    for (int m = 0; m < 8; m++) {
        int row = brow + ty * 8 + m;
#pragma unroll
        for (int c = 0; c < 8; c += 4) {
            int col = bcol + tx * 8 + c;
            float4 o;
            o.x = acc[m][c + 0] + bias[col + 0];
            o.y = acc[m][c + 1] + bias[col + 1];
            o.z = acc[m][c + 2] + bias[col + 2];
            o.w = acc[m][c + 3] + bias[col + 3];
            *(float4*)&Cm[(size_t)row * N + col] = o;
        }
    }
}

// ---------------------------------------------------------------------------
// Windowed attention with half-precision relative-position tables
// ---------------------------------------------------------------------------
// 8 halfs carried as a uint4; lane l reinterpreted as __half2
struct H8 { uint4 u; };
__device__ __forceinline__ H8 ldt(const __half* __restrict__ p) {
    H8 r; r.u = *(const uint4*)p; return r;
}
__device__ __forceinline__ __half2 lane(const H8& a, int l) {
    unsigned w = (l == 0) ? a.u.x : (l == 1) ? a.u.y : (l == 2) ? a.u.z : a.u.w;
    return *reinterpret_cast<const __half2*>(&w);
}
__device__ __forceinline__ __half2 sum6(const H8& a0, const H8& a1, const H8& a2,
                                        const H8& a3, const H8& a4, const H8& a5, int l) {
    return __hadd2(__hadd2(__hadd2(lane(a0, l), lane(a1, l)),
                           __hadd2(lane(a2, l), lane(a3, l))),
                   __hadd2(lane(a4, l), lane(a5, l)));
}

// dynamic smem layout (float offsets):
//   sk     [32*320] @ 0      (fp32 K, padded: h-stride 20 floats)
//   satt   [32*256] @ 10240
//   scoord [192]    @ 18432
//   spt    [32] int @ 18624
//   sidx2  [1024]u2 @ 18656  (ends 20704)
//   skh    [32*256] halfs @ float-offset 20704 (4096 floats)
#define ATTN_SMEM_FLOATS 24800
#define ATTN_SMEM_BYTES (ATTN_SMEM_FLOATS * 4)

__global__ __launch_bounds__(256, 2) void win_attn(
    const float* __restrict__ n_coords, const int* __restrict__ n2n)
{
    extern __shared__ float smem[];
    float* sk = smem;
    float* satt = smem + 10240;
    float* scoord = smem + 18432;
    int* spt = (int*)(smem + 18624);
    uint2* sidx2 = (uint2*)(smem + 18656);
    __half* skh = (__half*)(smem + 20704);

    const int tid = threadIdx.x;
    const int w = blockIdx.x;

    if (tid < KWIN) spt[tid] = n2n[w * KWIN + tid];
    __syncthreads();

    if (tid < 192) {
        int i = tid / 6, d = tid % 6;
        float s = (d < 3) ? QSF : CQSF;
        scoord[tid] = n_coords[(size_t)spt[i] * 6 + d] * s;
    }
    // stage K rows: fp32 padded + half copy (coalesced global reads)
    {
        const int h = tid >> 4, c = tid & 15;
        for (int j = 0; j < KWIN; ++j) {
            float kv = g_qkv[(size_t)spt[j] * 768 + 256 + tid];
            sk[j * 320 + h * 20 + c] = kv;
            skh[j * 256 + tid] = __float2half(kv);
        }
    }
    __syncthreads();

    // precompute packed relative indices per (i,j) pair
#pragma unroll
    for (int r = 0; r < 4; ++r) {
        int p = r * 256 + tid;
        int i = p >> 5, j = p & 31;
        const float* ci = scoord + i * 6;
        const float* cj = scoord + j * 6;
        int l[6];
#pragma unroll
        for (int d = 0; d < 3; d++) {
            int v = (int)floorf(ci[d] - cj[d]) + LXYZ / 2;
            l[d] = min(max(v, 0), LXYZ - 1);
        }
#pragma unroll
        for (int d = 0; d < 3; d++) {
            int v = (int)floorf(ci[3 + d] - cj[3 + d]) + LRGB / 2;
            l[3 + d] = min(max(v, 0), LRGB - 1);
        }
        unsigned lo = (unsigned)l[0] | ((unsigned)l[1] << 8) |
                      ((unsigned)l[2] << 16) | ((unsigned)l[3] << 24);
        unsigned hi = (unsigned)l[4] | ((unsigned)l[5] << 8);
        sidx2[p] = make_uint2(lo, hi);
    }
    __syncthreads();

    // each thread owns rows (i,h); 512 rows total, 2 per thread
    for (int r = 0; r < 2; ++r) {
        const int row = r * 256 + tid;
        const int i = row >> 4;
        const int h = row & 15;
        const int hb = h * 16;
        const int pt = spt[i];

        const __half* tKX = g_tabh + T_KX + hb;
        const __half* tQX = g_tabh + T_QX + hb;
        const __half* tVX = g_tabh + T_VX + hb;
        const __half* tKR = g_tabh + T_KR + hb;
        const __half* tQR = g_tabh + T_QR + hb;
        const __half* tVR = g_tabh + T_VR + hb;

        // q row (scaled) in fp32 regs + half2 copy
        float qf[16];
        __half2 qh[8];
        {
            const float4* qp = (const float4*)(g_qkv + (size_t)pt * 768 + hb);
#pragma unroll
            for (int t = 0; t < 4; t++) {
                float4 v = qp[t];
                qf[t * 4 + 0] = v.x * QK_SCALE; qf[t * 4 + 1] = v.y * QK_SCALE;
                qf[t * 4 + 2] = v.z * QK_SCALE; qf[t * 4 + 3] = v.w * QK_SCALE;
            }
#pragma unroll
            for (int k = 0; k < 8; k++)
                qh[k] = __floats2half2_rn(qf[2 * k], qf[2 * k + 1]);
        }

        // ---- logits ----
        for (int j = 0; j < KWIN; ++j) {
            const uint2 pk = sidx2[i * 32 + j];
            const int r0 = (int)(pk.x & 255) << 8;
            const int r1 = (int)(40 + ((pk.x >> 8) & 255)) << 8;
            const int r2 = (int)(80 + ((pk.x >> 16) & 255)) << 8;
            const int r3 = (int)(pk.x >> 24) << 8;
            const int r4 = (int)(32 + (pk.y & 255)) << 8;
            const int r5 = (int)(64 + ((pk.y >> 8) & 255)) << 8;

            // fp32 main q.k dot
            const float* kj = sk + j * 320 + h * 20;
            float facc = 0.f;
#pragma unroll
            for (int t = 0; t < 4; t++) {
                float4 kv = *(const float4*)(kj + 4 * t);
                facc += qf[4 * t + 0] * kv.x + qf[4 * t + 1] * kv.y +
                        qf[4 * t + 2] * kv.z + qf[4 * t + 3] * kv.w;
            }

            // half table dots (two 8-half chunks)
            const __half* khp = skh + j * 256 + hb;
#pragma unroll
            for (int c = 0; c < 2; c++) {
                H8 a0 = ldt(tKX + r0 + 8 * c), a1 = ldt(tKX + r1 + 8 * c),
                   a2 = ldt(tKX + r2 + 8 * c), a3 = ldt(tKR + r3 + 8 * c),
                   a4 = ldt(tKR + r4 + 8 * c), a5 = ldt(tKR + r5 + 8 * c);
                H8 b0 = ldt(tQX + r0 + 8 * c), b1 = ldt(tQX + r1 + 8 * c),
                   b2 = ldt(tQX + r2 + 8 * c), b3 = ldt(tQR + r3 + 8 * c),
                   b4 = ldt(tQR + r4 + 8 * c), b5 = ldt(tQR + r5 + 8 * c);
                H8 kk = ldt(khp + 8 * c);
                __half2 hq = __float2half2_rn(0.f);
                __half2 hk = hq;
#pragma unroll
                for (int l = 0; l < 4; l++) {
                    __half2 qs = sum6(a0, a1, a2, a3, a4, a5, l);
                    __half2 ks = sum6(b0, b1, b2, b3, b4, b5, l);
                    hq = __hfma2(qh[c * 4 + l], qs, hq);
                    hk = __hfma2(lane(kk, l), ks, hk);
                }
                float2 f = __half22float2(__hadd2(hq, hk));
                facc += f.x + f.y;
            }
            satt[j * 256 + tid] = facc;
        }

        // ---- softmax over j ----
        float mmax = -1e30f;
        for (int j = 0; j < KWIN; ++j) mmax = fmaxf(mmax, satt[j * 256 + tid]);
        float ssum = 0.f;
        for (int j = 0; j < KWIN; ++j) {
            float e = __expf(satt[j * 256 + tid] - mmax);
            satt[j * 256 + tid] = e;
            ssum += e;
        }
        const float inv = 1.0f / ssum;

        // ---- output ----
        float of[16];
#pragma unroll
        for (int e = 0; e < 16; e++) of[e] = 0.f;
        __half2 oh[8];
#pragma unroll
        for (int k = 0; k < 8; k++) oh[k] = __float2half2_rn(0.f);

        for (int j = 0; j < KWIN; ++j) {
            const float a = satt[j * 256 + tid] * inv;
            const __half2 ah = __float2half2_rn(a);
            const uint2 pk = sidx2[i * 32 + j];
            const int r0 = (int)(pk.x & 255) << 8;
            const int r1 = (int)(40 + ((pk.x >> 8) & 255)) << 8;
            const int r2 = (int)(80 + ((pk.x >> 16) & 255)) << 8;
            const int r3 = (int)(pk.x >> 24) << 8;
            const int r4 = (int)(32 + (pk.y & 255)) << 8;
            const int r5 = (int)(64 + ((pk.y >> 8) & 255)) << 8;

            // half table accumulation
#pragma unroll
            for (int c = 0; c < 2; c++) {
                H8 v0 = ldt(tVX + r0 + 8 * c), v1 = ldt(tVX + r1 + 8 * c),
                   v2 = ldt(tVX + r2 + 8 * c), v3 = ldt(tVR + r3 + 8 * c),
                   v4 = ldt(tVR + r4 + 8 * c), v5 = ldt(tVR + r5 + 8 * c);
#pragma unroll
                for (int l = 0; l < 4; l++) {
                    __half2 s = sum6(v0, v1, v2, v3, v4, v5, l);
                    oh[c * 4 + l] = __hfma2(ah, s, oh[c * 4 + l]);
                }
            }
            // fp32 a*v
            const float4* vp = (const float4*)(g_qkv + (size_t)spt[j] * 768 + 512 + hb);
#pragma unroll
            for (int t = 0; t < 4; t++) {
                float4 vv = vp[t];
                of[4 * t + 0] += a * vv.x; of[4 * t + 1] += a * vv.y;
                of[4 * t + 2] += a * vv.z; of[4 * t + 3] += a * vv.w;
            }
        }

        // merge half table part into fp32 output
#pragma unroll
        for (int k = 0; k < 8; k++) {
            float2 f = __half22float2(oh[k]);
            of[2 * k + 0] += f.x;
            of[2 * k + 1] += f.y;
        }

        float4* op = (float4*)(g_mid + (size_t)pt * CDIM + hb);
#pragma unroll
        for (int t = 0; t < 4; t++)
            op[t] = make_float4(of[4 * t], of[4 * t + 1], of[4 * t + 2], of[4 * t + 3]);
    }
}

// ---------------------------------------------------------------------------
extern "C" void kernel_launch(void* const* d_in, const int* in_sizes, int n_in,
                              void* d_out, int out_size)
{
    const float* feats    = (const float*)d_in[0];
    const float* n_coords = (const float*)d_in[1];
    const int*   n2n      = (const int*)d_in[2];
    const float* q_xyz    = (const float*)d_in[3];
    const float* k_xyz    = (const float*)d_in[4];
    const float* v_xyz    = (const float*)d_in[5];
    const float* q_rgb    = (const float*)d_in[6];
    const float* k_rgb    = (const float*)d_in[7];
    const float* v_rgb    = (const float*)d_in[8];
    const float* qkv_w    = (const float*)d_in[9];
    const float* qkv_b    = (const float*)d_in[10];
    const float* proj_w   = (const float*)d_in[11];
    const float* proj_b   = (const float*)d_in[12];
    float* out = (float*)d_out;

    float *qkv_p = nullptr, *mid_p = nullptr;
    cudaGetSymbolAddress((void**)&qkv_p, g_qkv);
    cudaGetSymbolAddress((void**)&mid_p, g_mid);

    cudaFuncSetAttribute(win_attn, cudaFuncAttributeMaxDynamicSharedMemorySize,
                         ATTN_SMEM_BYTES);

    // 0) convert tables to fp16
    cvt_tabs<<<120, 256>>>(k_xyz, q_xyz, v_xyz, k_rgb, q_rgb, v_rgb);

    // 1) QKV projection: [65536,256] x [768,256]^T
    dim3 g1(768 / 128, NPTS / 128);
    sgemm_nt<<<g1, 256>>>(feats, qkv_w, qkv_b, qkv_p, NPTS, 768, CDIM);

    // 2) windowed attention
    win_attn<<<NWIN, 256, ATTN_SMEM_BYTES>>>(n_coords, n2n);

    // 3) output projection: [65536,256] x [256,256]^T
    dim3 g2(CDIM / 128, NPTS / 128);
    sgemm_nt<<<g2, 256>>>(mid_p, proj_w, proj_b, out, NPTS, CDIM, CDIM);
}

// round 6
// speedup vs baseline: 3.6224x; 1.3091x over previous
#include <cuda_runtime.h>
#include <cuda_fp16.h>
#include <math.h>

#define NPTS 65536
#define CDIM 256
#define HEADS 16
#define HD 16
#define KWIN 32
#define NWIN 2048
#define LXYZ 40
#define LRGB 32
#define QSF 4.0f
#define CQSF 8.0f
#define QK_SCALE 0.25f

// half-table layout offsets (in halfs). Row layout TRANSPOSED: [row][c][h][8]
#define T_KX 0
#define T_QX 30720
#define T_VX 61440
#define T_KR 92160
#define T_QR 116736
#define T_VR 141312
#define T_TOT 165888

// Scratch (allocation-free rule: device globals)
__device__ float g_qkv[(size_t)NPTS * 768];
__device__ float g_mid[(size_t)NPTS * CDIM];
__device__ __align__(16) __half g_tabh[T_TOT];

// packed f32x2 FMA: c += a * b (lanewise on two fp32 packed in 64-bit regs)
#define FMA2(c, a, b) \
    asm("fma.rn.f32x2 %0, %1, %2, %0;" : "+l"(c) : "l"(a), "l"(b))

// ---------------------------------------------------------------------------
// Convert fp32 tables to fp16 with transposed row layout [row][c][h][8halfs]
// src element i within one table: row=i>>8, h=(i>>4)&15, c=(i>>3)&1, e=i&7
// dst = (row<<8) | (c<<7) | (h<<3) | e
// ---------------------------------------------------------------------------
__global__ void cvt_tabs(const float* __restrict__ kx, const float* __restrict__ qx,
                         const float* __restrict__ vx, const float* __restrict__ kr,
                         const float* __restrict__ qr, const float* __restrict__ vr)
{
    int i = blockIdx.x * 256 + threadIdx.x;
    int dst = (i & ~255) | ((i & 8) << 4) | ((i & 240) >> 1) | (i & 7);
    if (i < 30720) {
        g_tabh[T_KX + dst] = __float2half(kx[i]);
        g_tabh[T_QX + dst] = __float2half(qx[i]);
        g_tabh[T_VX + dst] = __float2half(vx[i]);
    }
    if (i < 24576) {
        g_tabh[T_KR + dst] = __float2half(kr[i]);
        g_tabh[T_QR + dst] = __float2half(qr[i]);
        g_tabh[T_VR + dst] = __float2half(vr[i]);
    }
}

// ---------------------------------------------------------------------------
// SGEMM: C[M,N] = A[M,K] @ W[N,K]^T + bias[N]
// 128x128 tile, BK=8, 256 threads, 8x8 per thread, double-buffered smem,
// packed f32x2 FMA inner loop.
// ---------------------------------------------------------------------------
__global__ __launch_bounds__(256, 2) void sgemm_nt(
    const float* __restrict__ A, const float* __restrict__ Wm,
    const float* __restrict__ bias, float* __restrict__ Cm,
    int M, int N, int Kd)
{
    __shared__ __align__(16) float As[2][8][128];
    __shared__ __align__(16) float Bs[2][8][128];
    const int tid = threadIdx.x;
    const int tx = tid & 15;
    const int ty = tid >> 4;
    const int brow = blockIdx.y * 128;
    const int bcol = blockIdx.x * 128;
    const int lrow = tid >> 1;
    const int lcol = (tid & 1) * 4;

    const float* Ap = A + (size_t)(brow + lrow) * Kd + lcol;
    const float* Wp = Wm + (size_t)(bcol + lrow) * Kd + lcol;

    unsigned long long acc2[8][4];
#pragma unroll
    for (int m = 0; m < 8; m++)
#pragma unroll
        for (int p = 0; p < 4; p++) acc2[m][p] = 0ull;

    {
        float4 av = *(const float4*)Ap;
        float4 wv = *(const float4*)Wp;
        As[0][lcol + 0][lrow] = av.x; As[0][lcol + 1][lrow] = av.y;
        As[0][lcol + 2][lrow] = av.z; As[0][lcol + 3][lrow] = av.w;
        Bs[0][lcol + 0][lrow] = wv.x; Bs[0][lcol + 1][lrow] = wv.y;
        Bs[0][lcol + 2][lrow] = wv.z; Bs[0][lcol + 3][lrow] = wv.w;
    }
    __syncthreads();

    const int nT = Kd / 8;
    for (int n = 0; n < nT; n++) {
        const int b = n & 1;
        float4 av2, wv2;
        const bool more = (n + 1 < nT);
        if (more) {
            av2 = *(const float4*)(Ap + (n + 1) * 8);
            wv2 = *(const float4*)(Wp + (n + 1) * 8);
        }
#pragma unroll
        for (int k = 0; k < 8; k++) {
            const ulonglong2* bp = (const ulonglong2*)&Bs[b][k][tx * 8];
            ulonglong2 b01 = bp[0];
            ulonglong2 b23 = bp[1];
#pragma unroll
            for (int m = 0; m < 8; m++) {
                unsigned int ai = __float_as_uint(As[b][k][ty * 8 + m]);
                unsigned long long aa;
                asm("mov.b64 %0, {%1, %1};" : "=l"(aa) : "r"(ai));
                FMA2(acc2[m][0], aa, b01.x);
                FMA2(acc2[m][1], aa, b01.y);
                FMA2(acc2[m][2], aa, b23.x);
                FMA2(acc2[m][3], aa, b23.y);
            }
        }
        if (more) {
            const int b2 = b ^ 1;
            As[b2][lcol + 0][lrow] = av2.x; As[b2][lcol + 1][lrow] = av2.y;
            As[b2][lcol + 2][lrow] = av2.z; As[b2][lcol + 3][lrow] = av2.w;
            Bs[b2][lcol + 0][lrow] = wv2.x; Bs[b2][lcol + 1][lrow] = wv2.y;
            Bs[b2][lcol + 2][lrow] = wv2.z; Bs[b2][lcol + 3][lrow] = wv2.w;
        }
        __syncthreads();
    }

#pragma unroll
    for (int m = 0; m < 8; m++) {
        int row = brow + ty * 8 + m;
#pragma unroll
        for (int p = 0; p < 4; p += 2) {
            int col = bcol + tx * 8 + p * 2;
            float c0, c1, c2, c3;
            asm("mov.b64 {%0, %1}, %2;" : "=f"(c0), "=f"(c1) : "l"(acc2[m][p]));
            asm("mov.b64 {%0, %1}, %2;" : "=f"(c2), "=f"(c3) : "l"(acc2[m][p + 1]));
            float4 o;
            o.x = c0 + bias[col + 0];
            o.y = c1 + bias[col + 1];
            o.z = c2 + bias[col + 2];
            o.w = c3 + bias[col + 3];
            *(float4*)&Cm[(size_t)row * N + col] = o;
        }
    }
}

// ---------------------------------------------------------------------------
// Windowed attention: fused single-pass (flash-style) with fp16 tables
// ---------------------------------------------------------------------------
struct H8 { uint4 u; };
__device__ __forceinline__ H8 ldt(const __half* __restrict__ p) {
    H8 r; r.u = *(const uint4*)p; return r;
}
__device__ __forceinline__ __half2 lane(const H8& a, int l) {
    unsigned w = (l == 0) ? a.u.x : (l == 1) ? a.u.y : (l == 2) ? a.u.z : a.u.w;
    return *reinterpret_cast<const __half2*>(&w);
}
__device__ __forceinline__ __half2 sum6(const H8& a0, const H8& a1, const H8& a2,
                                        const H8& a3, const H8& a4, const H8& a5, int l) {
    return __hadd2(__hadd2(__hadd2(lane(a0, l), lane(a1, l)),
                           __hadd2(lane(a2, l), lane(a3, l))),
                   __hadd2(lane(a4, l), lane(a5, l)));
}

// smem layout (float offsets):
//   sk     [32*320] @ 0       (fp32 K, h-stride 20 -> conflict-free LDS.128)
//   sv     [32*320] @ 10240   (fp32 V, same padding)
//   scoord [192]    @ 20480
//   spt    [32] int @ 20672
//   sidx2  [1024]u2 @ 20704   (2048 floats, ends 22752)
//   skh    [8192]h  @ 22752   (4096 floats, ends 26848)
#define ATTN_SMEM_FLOATS 26848
#define ATTN_SMEM_BYTES (ATTN_SMEM_FLOATS * 4)

__global__ __launch_bounds__(256, 2) void win_attn(
    const float* __restrict__ n_coords, const int* __restrict__ n2n)
{
    extern __shared__ float smem[];
    float* sk = smem;
    float* sv = smem + 10240;
    float* scoord = smem + 20480;
    int* spt = (int*)(smem + 20672);
    uint2* sidx2 = (uint2*)(smem + 20704);
    __half* skh = (__half*)(smem + 22752);

    const int tid = threadIdx.x;
    const int w = blockIdx.x;

    if (tid < KWIN) spt[tid] = n2n[w * KWIN + tid];
    __syncthreads();

    if (tid < 192) {
        int i = tid / 6, d = tid % 6;
        float s = (d < 3) ? QSF : CQSF;
        scoord[tid] = n_coords[(size_t)spt[i] * 6 + d] * s;
    }
    // stage K (fp32 padded + half) and V (fp32 padded); coalesced gmem reads
    {
        const int h = tid >> 4, c = tid & 15;
        for (int j = 0; j < KWIN; ++j) {
            size_t base = (size_t)spt[j] * 768;
            float kv = g_qkv[base + 256 + tid];
            float vv = g_qkv[base + 512 + tid];
            sk[j * 320 + h * 20 + c] = kv;
            sv[j * 320 + h * 20 + c] = vv;
            skh[j * 256 + tid] = __float2half(kv);
        }
    }
    __syncthreads();

    // packed relative indices per (i,j)
#pragma unroll
    for (int r = 0; r < 4; ++r) {
        int p = r * 256 + tid;
        int i = p >> 5, j = p & 31;
        const float* ci = scoord + i * 6;
        const float* cj = scoord + j * 6;
        int l[6];
#pragma unroll
        for (int d = 0; d < 3; d++) {
            int v = (int)floorf(ci[d] - cj[d]) + LXYZ / 2;
            l[d] = min(max(v, 0), LXYZ - 1);
        }
#pragma unroll
        for (int d = 0; d < 3; d++) {
            int v = (int)floorf(ci[3 + d] - cj[3 + d]) + LRGB / 2;
            l[3 + d] = min(max(v, 0), LRGB - 1);
        }
        unsigned lo = (unsigned)l[0] | ((unsigned)l[1] << 8) |
                      ((unsigned)l[2] << 16) | ((unsigned)l[3] << 24);
        unsigned hi = (unsigned)l[4] | ((unsigned)l[5] << 8);
        sidx2[p] = make_uint2(lo, hi);
    }
    __syncthreads();

    // each thread owns rows (i,h); 512 rows total, 2 per thread
    for (int r = 0; r < 2; ++r) {
        const int row = r * 256 + tid;
        const int i = row >> 4;
        const int h = row & 15;
        const int hb = h * 16;   // skh / q / output base (halfs or floats)
        const int h8 = h * 8;    // transposed table base (halfs)
        const int pt = spt[i];

        const __half* tKX = g_tabh + T_KX + h8;
        const __half* tQX = g_tabh + T_QX + h8;
        const __half* tVX = g_tabh + T_VX + h8;
        const __half* tKR = g_tabh + T_KR + h8;
        const __half* tQR = g_tabh + T_QR + h8;
        const __half* tVR = g_tabh + T_VR + h8;

        // q row (scaled): fp32 + half2 copy
        float qf[16];
        __half2 qh[8];
        {
            const float4* qp = (const float4*)(g_qkv + (size_t)pt * 768 + hb);
#pragma unroll
            for (int t = 0; t < 4; t++) {
                float4 v = qp[t];
                qf[t * 4 + 0] = v.x * QK_SCALE; qf[t * 4 + 1] = v.y * QK_SCALE;
                qf[t * 4 + 2] = v.z * QK_SCALE; qf[t * 4 + 3] = v.w * QK_SCALE;
            }
#pragma unroll
            for (int k = 0; k < 8; k++)
                qh[k] = __floats2half2_rn(qf[2 * k], qf[2 * k + 1]);
        }

        // softmax baseline: main dot vs j=0 (shift only; weights unchanged)
        float bshift = 0.f;
        {
            const float* k0 = sk + h * 20;
#pragma unroll
            for (int t = 0; t < 4; t++) {
                float4 kv = *(const float4*)(k0 + 4 * t);
                bshift += qf[4 * t + 0] * kv.x + qf[4 * t + 1] * kv.y +
                          qf[4 * t + 2] * kv.z + qf[4 * t + 3] * kv.w;
            }
        }

        float ssum = 0.f;
        float of[16];
#pragma unroll
        for (int e = 0; e < 16; e++) of[e] = 0.f;

        // ---- fused single pass over j ----
        for (int j = 0; j < KWIN; ++j) {
            const uint2 pk = sidx2[i * 32 + j];
            const int r0 = (int)(pk.x & 255) << 8;
            const int r1 = (int)(40 + ((pk.x >> 8) & 255)) << 8;
            const int r2 = (int)(80 + ((pk.x >> 16) & 255)) << 8;
            const int r3 = (int)(pk.x >> 24) << 8;
            const int r4 = (int)(32 + (pk.y & 255)) << 8;
            const int r5 = (int)(64 + ((pk.y >> 8) & 255)) << 8;

            // fp32 main q.k dot
            const float* kj = sk + j * 320 + h * 20;
            float facc = 0.f;
#pragma unroll
            for (int t = 0; t < 4; t++) {
                float4 kv = *(const float4*)(kj + 4 * t);
                facc += qf[4 * t + 0] * kv.x + qf[4 * t + 1] * kv.y +
                        qf[4 * t + 2] * kv.z + qf[4 * t + 3] * kv.w;
            }

            // half table logit part
            const __half* khp = skh + j * 256 + hb;
#pragma unroll
            for (int c = 0; c < 2; c++) {
                const int co = c << 7;
                H8 a0 = ldt(tKX + r0 + co), a1 = ldt(tKX + r1 + co),
                   a2 = ldt(tKX + r2 + co), a3 = ldt(tKR + r3 + co),
                   a4 = ldt(tKR + r4 + co), a5 = ldt(tKR + r5 + co);
                H8 b0 = ldt(tQX + r0 + co), b1 = ldt(tQX + r1 + co),
                   b2 = ldt(tQX + r2 + co), b3 = ldt(tQR + r3 + co),
                   b4 = ldt(tQR + r4 + co), b5 = ldt(tQR + r5 + co);
                H8 kk = ldt(khp + 8 * c);
                __half2 hq = __float2half2_rn(0.f);
                __half2 hk = hq;
#pragma unroll
                for (int l = 0; l < 4; l++) {
                    __half2 qs = sum6(a0, a1, a2, a3, a4, a5, l);
                    __half2 ks = sum6(b0, b1, b2, b3, b4, b5, l);
                    hq = __hfma2(qh[c * 4 + l], qs, hq);
                    hk = __hfma2(lane(kk, l), ks, hk);
                }
                float2 f = __half22float2(__hadd2(hq, hk));
                facc += f.x + f.y;
            }

            const float a = __expf(facc - bshift);
            ssum += a;

            // value side: fp32 accumulate of a*(v + sum6(vtab))
            const float* vj = sv + j * 320 + h * 20;
#pragma unroll
            for (int c = 0; c < 2; c++) {
                const int co = c << 7;
                H8 v0 = ldt(tVX + r0 + co), v1 = ldt(tVX + r1 + co),
                   v2 = ldt(tVX + r2 + co), v3 = ldt(tVR + r3 + co),
                   v4 = ldt(tVR + r4 + co), v5 = ldt(tVR + r5 + co);
                float4 va = *(const float4*)(vj + 8 * c);
                float4 vb = *(const float4*)(vj + 8 * c + 4);
                float2 t0 = __half22float2(sum6(v0, v1, v2, v3, v4, v5, 0));
                float2 t1 = __half22float2(sum6(v0, v1, v2, v3, v4, v5, 1));
                float2 t2 = __half22float2(sum6(v0, v1, v2, v3, v4, v5, 2));
                float2 t3 = __half22float2(sum6(v0, v1, v2, v3, v4, v5, 3));
                float* o = of + c * 8;
                o[0] += a * (va.x + t0.x); o[1] += a * (va.y + t0.y);
                o[2] += a * (va.z + t1.x); o[3] += a * (va.w + t1.y);
                o[4] += a * (vb.x + t2.x); o[5] += a * (vb.y + t2.y);
                o[6] += a * (vb.z + t3.x); o[7] += a * (vb.w + t3.y);
            }
        }

        const float inv = 1.0f / ssum;
        float4* op = (float4*)(g_mid + (size_t)pt * CDIM + hb);
#pragma unroll
        for (int t = 0; t < 4; t++)
            op[t] = make_float4(of[4 * t] * inv, of[4 * t + 1] * inv,
                                of[4 * t + 2] * inv, of[4 * t + 3] * inv);
    }
}

// ---------------------------------------------------------------------------
extern "C" void kernel_launch(void* const* d_in, const int* in_sizes, int n_in,
                              void* d_out, int out_size)
{
    const float* feats    = (const float*)d_in[0];
    const float* n_coords = (const float*)d_in[1];
    const int*   n2n      = (const int*)d_in[2];
    const float* q_xyz    = (const float*)d_in[3];
    const float* k_xyz    = (const float*)d_in[4];
    const float* v_xyz    = (const float*)d_in[5];
    const float* q_rgb    = (const float*)d_in[6];
    const float* k_rgb    = (const float*)d_in[7];
    const float* v_rgb    = (const float*)d_in[8];
    const float* qkv_w    = (const float*)d_in[9];
    const float* qkv_b    = (const float*)d_in[10];
    const float* proj_w   = (const float*)d_in[11];
    const float* proj_b   = (const float*)d_in[12];
    float* out = (float*)d_out;

    float *qkv_p = nullptr, *mid_p = nullptr;
    cudaGetSymbolAddress((void**)&qkv_p, g_qkv);
    cudaGetSymbolAddress((void**)&mid_p, g_mid);

    cudaFuncSetAttribute(win_attn, cudaFuncAttributeMaxDynamicSharedMemorySize,
                         ATTN_SMEM_BYTES);

    // 0) convert tables to fp16 (transposed rows)
    cvt_tabs<<<120, 256>>>(k_xyz, q_xyz, v_xyz, k_rgb, q_rgb, v_rgb);

    // 1) QKV projection: [65536,256] x [768,256]^T
    dim3 g1(768 / 128, NPTS / 128);
    sgemm_nt<<<g1, 256>>>(feats, qkv_w, qkv_b, qkv_p, NPTS, 768, CDIM);

    // 2) windowed attention (fused)
    win_attn<<<NWIN, 256, ATTN_SMEM_BYTES>>>(n_coords, n2n);

    // 3) output projection: [65536,256] x [256,256]^T
    dim3 g2(CDIM / 128, NPTS / 128);
    sgemm_nt<<<g2, 256>>>(mid_p, proj_w, proj_b, out, NPTS, CDIM, CDIM);
}